// round 3
// baseline (speedup 1.0000x reference)
#include <cuda_runtime.h>
#include <cuda_bf16.h>
#include <cstddef>

// ---------------------------------------------------------------------------
// Problem constants
// ---------------------------------------------------------------------------
#define NB     2048     // batch
#define LX     168      // encoder steps
#define FF     64       // encoder features
#define HID    256      // hidden
#define LY     72       // decoder steps
#define FT     22       // future feats
#define FOUTV  10       // output size
#define DECIN  32       // FT + FOUTV
#define REGH   128
#define CLSH   128

#define BT     16       // batch rows per CTA
#define NCTA   (NB / BT)        // 128
#define NTHR   256
#define RPAIR  8        // BT/2 row pairs
#define HSTR   9        // float2 stride per k-row (padding: odd -> low conflicts)

// ---------------------------------------------------------------------------
// Packed weight scratch (device globals -- no allocation allowed)
//   W*rz[k][u] = (w_r(u,k), w_z(u,k)) ; W*n[k][u] = w_n(u,k)
// ---------------------------------------------------------------------------
__device__ float2 g_encWrz[HID * HID];    // 512 KB
__device__ float  g_encWn [HID * HID];    // 256 KB
__device__ float2 g_encIrz[FF * HID];     // 128 KB
__device__ float  g_encIn [FF * HID];     //  64 KB
__device__ float2 g_decWrz[HID * HID];
__device__ float  g_decWn [HID * HID];
__device__ float2 g_decIrz[DECIN * HID];
__device__ float  g_decIn [DECIN * HID];
__device__ float  g_hW0T[HID * 256];      // head layer0, units 0..127 = temphr, 128..255 = class
__device__ float  g_hb0 [256];
__device__ float  g_hW1 [FOUTV * REGH];   // rows 0..1 temphr, 2..9 class
__device__ float  g_hb1 [FOUTV];
__device__ float4 g_encB[HID];            // (bir+bhr, biz+bhz, bin, bhn)
__device__ float4 g_decB[HID];

// ---------------------------------------------------------------------------
// f32x2 packed-FMA helpers (sm_103a: fma.rn.f32x2)
// ---------------------------------------------------------------------------
typedef unsigned long long ull;

__device__ __forceinline__ ull fma2(ull a, ull b, ull c) {
    ull d;
    asm("fma.rn.f32x2 %0, %1, %2, %3;" : "=l"(d) : "l"(a), "l"(b), "l"(c));
    return d;
}
__device__ __forceinline__ ull bcast2(float x) {
    ull d; unsigned int xi = __float_as_uint(x);
    asm("mov.b64 %0, {%1, %2};" : "=l"(d) : "r"(xi), "r"(xi));
    return d;
}
__device__ __forceinline__ float2 unp2(ull v) {
    unsigned int lo, hi;
    asm("mov.b64 {%0, %1}, %2;" : "=r"(lo), "=r"(hi) : "l"(v));
    return make_float2(__uint_as_float(lo), __uint_as_float(hi));
}

__device__ __forceinline__ float sigf(float x) {
    return __fdividef(1.0f, 1.0f + __expf(-x));
}
__device__ __forceinline__ float tanhfast(float x) {
    return __fdividef(2.0f, 1.0f + __expf(-2.0f * x)) - 1.0f;
}
__device__ __forceinline__ float smelu(float x) {
    if (x >= 1.1f) return x;
    if (x <= -1.1f) return 0.0f;
    float u = x + 1.1f;
    return u * u * (1.0f / 4.4f);
}

// ---------------------------------------------------------------------------
// Setup kernel: transpose/pack weights into the streaming-friendly layouts.
// One thread per (k, u) of a 256x256 grid; small arrays guarded by id.
// ---------------------------------------------------------------------------
__global__ void setup_kernel(
    const float* __restrict__ encWih, const float* __restrict__ encWhh,
    const float* __restrict__ encBih, const float* __restrict__ encBhh,
    const float* __restrict__ decWih, const float* __restrict__ decWhh,
    const float* __restrict__ decBih, const float* __restrict__ decBhh,
    const float* __restrict__ thW0,  const float* __restrict__ thB0,
    const float* __restrict__ thW1,  const float* __restrict__ thB1,
    const float* __restrict__ clW0,  const float* __restrict__ clB0,
    const float* __restrict__ clW1,  const float* __restrict__ clB1)
{
    int id = blockIdx.x * blockDim.x + threadIdx.x;   // 0 .. 65535
    int u  = id & 255;
    int k  = id >> 8;                                  // 0 .. 255

    // recurrent weights (Whh is (3H, H) row-major; gates r,z,n in that order)
    g_encWrz[k * HID + u] = make_float2(encWhh[u * HID + k], encWhh[(HID + u) * HID + k]);
    g_encWn [k * HID + u] = encWhh[(2 * HID + u) * HID + k];
    g_decWrz[k * HID + u] = make_float2(decWhh[u * HID + k], decWhh[(HID + u) * HID + k]);
    g_decWn [k * HID + u] = decWhh[(2 * HID + u) * HID + k];

    // head layer-0 combined (th units 0..127, cl units 128..255)
    g_hW0T[k * 256 + u] = (u < REGH) ? thW0[u * HID + k] : clW0[(u - REGH) * HID + k];

    if (k < FF) {
        g_encIrz[k * HID + u] = make_float2(encWih[u * FF + k], encWih[(HID + u) * FF + k]);
        g_encIn [k * HID + u] = encWih[(2 * HID + u) * FF + k];
    }
    if (k < DECIN) {
        g_decIrz[k * HID + u] = make_float2(decWih[u * DECIN + k], decWih[(HID + u) * DECIN + k]);
        g_decIn [k * HID + u] = decWih[(2 * HID + u) * DECIN + k];
    }
    if (id < HID) {
        g_encB[id] = make_float4(encBih[id] + encBhh[id],
                                 encBih[HID + id] + encBhh[HID + id],
                                 encBih[2 * HID + id],
                                 encBhh[2 * HID + id]);
        g_decB[id] = make_float4(decBih[id] + decBhh[id],
                                 decBih[HID + id] + decBhh[HID + id],
                                 decBih[2 * HID + id],
                                 decBhh[2 * HID + id]);
        g_hb0[id] = (id < REGH) ? thB0[id] : clB0[id - REGH];
    }
    if (id < FOUTV * REGH) {
        int o = id >> 7, kk = id & 127;
        g_hW1[id] = (o < 2) ? thW1[o * REGH + kk] : clW1[(o - 2) * CLSH + kk];
    }
    if (id < FOUTV) g_hb1[id] = (id < 2) ? thB1[id] : clB1[id - 2];
}

// ---------------------------------------------------------------------------
// GEMM accumulate: for thread's unit t, accumulate r/z/n gate partials over K
// src: packed [k][rowpair] float2 activations (broadcast LDS)
// ---------------------------------------------------------------------------
__device__ __forceinline__ void accum_rzn(
    const float2* __restrict__ Wrz, const float* __restrict__ Wn,
    const ull* __restrict__ src, int K, int t,
    ull aR[RPAIR], ull aZ[RPAIR], ull aN[RPAIR])
{
#pragma unroll 4
    for (int k = 0; k < K; k++) {
        float2 w2 = Wrz[k * HID + t];
        float  wn = Wn [k * HID + t];
        ull br = bcast2(w2.x), bz = bcast2(w2.y), bn = bcast2(wn);
        const ull* s = src + k * HSTR;
#pragma unroll
        for (int rp = 0; rp < RPAIR; rp++) {
            ull hp = s[rp];
            aR[rp] = fma2(hp, br, aR[rp]);
            aZ[rp] = fma2(hp, bz, aZ[rp]);
            aN[rp] = fma2(hp, bn, aN[rp]);
        }
    }
}

// ---------------------------------------------------------------------------
// Persistent recurrent kernel: one CTA per 16 batch rows, full time loop.
// ---------------------------------------------------------------------------
__global__ void __launch_bounds__(NTHR, 1) rnn_kernel(
    const float* __restrict__ x_f,   // (N, LX, FF)
    const float* __restrict__ y_t,   // (N, LY+1, FT)
    const float* __restrict__ p,     // (N, LY+1, FOUTV)
    float* __restrict__ out)         // (N, LY, FOUTV)
{
    __shared__ float2 hs [HID * HSTR];   // hidden state, packed row-pairs
    __shared__ float2 us [FF  * HSTR];   // step input, packed row-pairs
    __shared__ float2 aps[256 * HSTR];   // head-0 activations, packed

    const int t       = threadIdx.x;        // owns hidden unit t / head unit t
    const int rowbase = blockIdx.x * BT;

    float hreg[BT];
#pragma unroll
    for (int r = 0; r < BT; r++) hreg[r] = 0.0f;
#pragma unroll
    for (int rp = 0; rp < RPAIR; rp++) hs[t * HSTR + rp] = make_float2(0.0f, 0.0f);

    const ull* hsu = (const ull*)hs;
    const ull* usu = (const ull*)us;

    const float4 eb = g_encB[t];

    // ================= encoder =================
    for (int step = 0; step < LX; step++) {
        // load u tile: x_f[rowbase.., step, :] packed into us[k][rp]
        for (int idx = t; idx < FF * RPAIR; idx += NTHR) {
            int k = idx & (FF - 1), rp = idx >> 6;
            size_t base = ((size_t)(rowbase + 2 * rp) * LX + step) * FF + k;
            us[k * HSTR + rp] = make_float2(x_f[base], x_f[base + (size_t)LX * FF]);
        }
        __syncthreads();   // us ready; hs (prev step) visible

        ull aR[RPAIR], aZ[RPAIR], aGN[RPAIR], aHN[RPAIR];
        {
            ull bR = bcast2(eb.x), bZ = bcast2(eb.y), bGN = bcast2(eb.z), bHN = bcast2(eb.w);
#pragma unroll
            for (int rp = 0; rp < RPAIR; rp++) { aR[rp] = bR; aZ[rp] = bZ; aGN[rp] = bGN; aHN[rp] = bHN; }
        }
        accum_rzn(g_encWrz, g_encWn, hsu, HID, t, aR, aZ, aHN);   // hidden part (n -> aHN)
        accum_rzn(g_encIrz, g_encIn, usu, FF,  t, aR, aZ, aGN);   // input part  (n -> aGN)
        __syncthreads();   // all reads of hs/us done

        // gates + state update (old h kept in registers)
#pragma unroll
        for (int rp = 0; rp < RPAIR; rp++) {
            float2 vR = unp2(aR[rp]), vZ = unp2(aZ[rp]), vGN = unp2(aGN[rp]), vHN = unp2(aHN[rp]);
            float r0 = sigf(vR.x), z0 = sigf(vZ.x), n0 = tanhfast(vGN.x + r0 * vHN.x);
            float r1 = sigf(vR.y), z1 = sigf(vZ.y), n1 = tanhfast(vGN.y + r1 * vHN.y);
            float h0 = n0 + z0 * (hreg[2 * rp]     - n0);
            float h1 = n1 + z1 * (hreg[2 * rp + 1] - n1);
            hreg[2 * rp] = h0; hreg[2 * rp + 1] = h1;
            hs[t * HSTR + rp] = make_float2(h0, h1);
        }
        // next iteration's first __syncthreads orders these hs writes vs reads
    }

    // ================= decoder =================
    const float4 db = g_decB[t];
    const float  b0 = g_hb0[t];

    for (int i = 0; i < LY; i++) {
        const int j = (i == 0) ? 0 : (i - 1);
        // load dec input: concat(y_t[:, j, 0:22], p[:, j, 0:10]) -> 32 feats
        {
            int idx = t;                       // DECIN*RPAIR == 256 == NTHR
            int k = idx & (DECIN - 1), rp = idx >> 5;
            int r0 = rowbase + 2 * rp;
            float a, b;
            if (k < FT) {
                size_t base = ((size_t)r0 * (LY + 1) + j) * FT + k;
                a = y_t[base]; b = y_t[base + (size_t)(LY + 1) * FT];
            } else {
                size_t base = ((size_t)r0 * (LY + 1) + j) * FOUTV + (k - FT);
                a = p[base]; b = p[base + (size_t)(LY + 1) * FOUTV];
            }
            us[k * HSTR + rp] = make_float2(a, b);
        }
        __syncthreads();

        ull aR[RPAIR], aZ[RPAIR], aGN[RPAIR], aHN[RPAIR];
        {
            ull bR = bcast2(db.x), bZ = bcast2(db.y), bGN = bcast2(db.z), bHN = bcast2(db.w);
#pragma unroll
            for (int rp = 0; rp < RPAIR; rp++) { aR[rp] = bR; aZ[rp] = bZ; aGN[rp] = bGN; aHN[rp] = bHN; }
        }
        accum_rzn(g_decWrz, g_decWn, hsu, HID,   t, aR, aZ, aHN);
        accum_rzn(g_decIrz, g_decIn, usu, DECIN, t, aR, aZ, aGN);
        __syncthreads();   // reads of hs done -> safe to overwrite

#pragma unroll
        for (int rp = 0; rp < RPAIR; rp++) {
            float2 vR = unp2(aR[rp]), vZ = unp2(aZ[rp]), vGN = unp2(aGN[rp]), vHN = unp2(aHN[rp]);
            float r0 = sigf(vR.x), z0 = sigf(vZ.x), n0 = tanhfast(vGN.x + r0 * vHN.x);
            float r1 = sigf(vR.y), z1 = sigf(vZ.y), n1 = tanhfast(vGN.y + r1 * vHN.y);
            float h0 = n0 + z0 * (hreg[2 * rp]     - n0);
            float h1 = n1 + z1 * (hreg[2 * rp + 1] - n1);
            hreg[2 * rp] = h0; hreg[2 * rp + 1] = h1;
            hs[t * HSTR + rp] = make_float2(h0, h1);
        }
        __syncthreads();   // new h visible for the head GEMM

        // ---- head layer 0: a = smelu(h2 @ W0^T + b0), 256 combined units ----
        ull aA[RPAIR];
        {
            ull b0p = bcast2(b0);
#pragma unroll
            for (int rp = 0; rp < RPAIR; rp++) aA[rp] = b0p;
        }
#pragma unroll 4
        for (int k = 0; k < HID; k++) {
            ull bw = bcast2(g_hW0T[k * 256 + t]);
            const ull* s = hsu + k * HSTR;
#pragma unroll
            for (int rp = 0; rp < RPAIR; rp++) aA[rp] = fma2(s[rp], bw, aA[rp]);
        }
#pragma unroll
        for (int rp = 0; rp < RPAIR; rp++) {
            float2 v = unp2(aA[rp]);
            aps[t * HSTR + rp] = make_float2(smelu(v.x), smelu(v.y));
        }
        __syncthreads();   // aps ready

        // ---- head layer 1: 10 outputs x 16 rows = 160 dots of length 128 ----
        if (t < BT * FOUTV) {
            int row = t / FOUTV, o = t - row * FOUTV;
            int koff = (o < 2) ? 0 : REGH;
            const float* apf = (const float*)aps;   // flat: [(unit)*2*HSTR + row]
            const float* w   = &g_hW1[o * REGH];
            float s = g_hb1[o];
#pragma unroll 4
            for (int k = 0; k < REGH; k++)
                s += apf[(koff + k) * (2 * HSTR) + row] * w[k];
            out[((size_t)(rowbase + row) * LY + i) * FOUTV + o] = s;
        }
        // next iteration's first __syncthreads fences aps/us reuse
    }
}

// ---------------------------------------------------------------------------
// Launch. d_in order: x_f, x(unused), y_t, p, enc_Wih, enc_Whh, enc_bih,
// enc_bhh, dec_Wih, dec_Whh, dec_bih, dec_bhh, th_W0, th_b0, th_W1, th_b1,
// cl_W0, cl_b0, cl_W1, cl_b1
// ---------------------------------------------------------------------------
extern "C" void kernel_launch(void* const* d_in, const int* in_sizes, int n_in,
                              void* d_out, int out_size)
{
    const float* x_f    = (const float*)d_in[0];
    const float* y_t    = (const float*)d_in[2];
    const float* p      = (const float*)d_in[3];
    const float* encWih = (const float*)d_in[4];
    const float* encWhh = (const float*)d_in[5];
    const float* encBih = (const float*)d_in[6];
    const float* encBhh = (const float*)d_in[7];
    const float* decWih = (const float*)d_in[8];
    const float* decWhh = (const float*)d_in[9];
    const float* decBih = (const float*)d_in[10];
    const float* decBhh = (const float*)d_in[11];
    const float* thW0   = (const float*)d_in[12];
    const float* thB0   = (const float*)d_in[13];
    const float* thW1   = (const float*)d_in[14];
    const float* thB1   = (const float*)d_in[15];
    const float* clW0   = (const float*)d_in[16];
    const float* clB0   = (const float*)d_in[17];
    const float* clW1   = (const float*)d_in[18];
    const float* clB1   = (const float*)d_in[19];
    float* out = (float*)d_out;

    setup_kernel<<<256, 256>>>(encWih, encWhh, encBih, encBhh,
                               decWih, decWhh, decBih, decBhh,
                               thW0, thB0, thW1, thB1,
                               clW0, clB0, clW1, clB1);
    rnn_kernel<<<NCTA, NTHR>>>(x_f, y_t, p, out);
}